// round 13
// baseline (speedup 1.0000x reference)
#include <cuda_runtime.h>

// GlottalFlowTable — fixed shapes: B=32, S=524288, HOP=256, L=100, frames=2048
//
// R13: last open axis — samples/thread granularity sweep.
// Measured: 8/thr = 31.2-31.6us, 4/thr = 28.6-29.4us (5 runs). This tests
// 2/thr: gather wavefronts are granularity-invariant, but per-thread chains
// halve (8 gather LDGs) and twice as many warps feed the L1tex queues with
// smaller bursts — the same effect that made 4 beat 8. Cost: wp/out move to
// LDG.64/STG.64 (+~4% streaming wavefronts).
// Everything else identical to the R10 optimum (streaming hints, per-sample
// scalar-LDG bilinear gather, independent FMA trees).

constexpr int B      = 32;
constexpr int S      = 524288;
constexpr int HOP    = 256;
constexpr int L      = 100;
constexpr int FRAMES = S / HOP;    // 2048
constexpr int TROWS  = FRAMES + 1; // 2049
constexpr int S2     = S / 2;      // 262144 float2 per batch row

__global__ __launch_bounds__(256)
void glottal_flow_kernel(const float* __restrict__ wp,
                         const float* __restrict__ tables,
                         float* __restrict__ out)
{
    int i2 = blockIdx.x * 256 + threadIdx.x;   // global float2 index
    int b  = i2 >> 18;                         // / S2 (262144)
    int s  = (i2 & (S2 - 1)) << 1;             // sample index within batch row
    int f  = s >> 8;                           // frame (HOP = 256)
    int t  = s & (HOP - 1);                    // position within frame

    float2 w = __ldcs(reinterpret_cast<const float2*>(wp) + i2);  // streaming

    const float* rowF = tables + (size_t)(b * TROWS + f) * L; // floor frame row
    const float* rowC = rowF + L;                              // ceil frame row

    float wk[2] = {w.x, w.y};
    float r[2];

#pragma unroll
    for (int k = 0; k < 2; ++k) {
        float idx_raw = wk[k] * (float)L;
        int   fi      = (int)idx_raw;              // trunc toward zero (data >= 0)
        fi            = max(0, min(fi, L - 1));    // clip like reference
        float p       = idx_raw - (float)fi;
        int   fj      = fi + 1;
        if (fj == L) fj = 0;                       // padded column L == column 0

        float loF = __ldg(rowF + fi);
        float hiF = __ldg(rowF + fj);
        float loC = __ldg(rowC + fi);
        float hiC = __ldg(rowC + fj);

        float vF = fmaf(p, hiF - loF, loF);        // phase lerp, floor frame
        float vC = fmaf(p, hiC - loC, loC);        // phase lerp, ceil frame
        float p2 = (float)(t + k) * (1.0f / (float)HOP);
        r[k] = fmaf(p2, vC - vF, vF);              // frame lerp
    }

    __stcs(reinterpret_cast<float2*>(out) + i2,    // streaming store
           make_float2(r[0], r[1]));
}

extern "C" void kernel_launch(void* const* d_in, const int* in_sizes, int n_in,
                              void* d_out, int out_size)
{
    const float* wp     = (const float*)d_in[0];
    const float* tables = (const float*)d_in[1];
    float*       out    = (float*)d_out;

    constexpr int total2 = (B * S) / 2;            // 8,388,608 float2 work items
    glottal_flow_kernel<<<total2 / 256, 256>>>(wp, tables, out);
}

// round 14
// speedup vs baseline: 1.1815x; 1.1815x over previous
#include <cuda_runtime.h>

// GlottalFlowTable — fixed shapes: B=32, S=524288, HOP=256, L=100, frames=2048
//
// FINAL (= R7/R9/R10/R12; measured 28.6-29.4us kernel across five runs,
// best bench 31.2us). 4 samples/thread, per-sample scalar-LDG bilinear
// gather, float4 streaming I/O (__ldcs wp, __stcs out), independent per-k
// FMA trees.
//
// Complete design-space map (R1-R13):
//  - gather unit:  global LDG 28.8us | smem LDS 33.6us | shuffle 45.4us
//  - samples/thr:  2 -> 40.6us | 4 -> 28.8us | 8 -> 31.4us  (U-shaped)
//  - batch shape:  interleaved best; front-batch/persistent-pipeline worse
//  - cache:        streaming hints on wp/out best; cached wp regressed
//  - prefetch:     neutral (issue 47->54%, duration flat -> queue-bound)
//  - occupancy:    invariant 45-85%
// Floor: ~5.2M L1TEX wavefronts = 19.5us busy (measured 0.67 x dur, 5 runs);
// random-gather queueing caps density ~68%. All repackings are
// wavefront-invariant at 4B granularity or pay unrecoverable DRAM.

constexpr int B      = 32;
constexpr int S      = 524288;
constexpr int HOP    = 256;
constexpr int L      = 100;
constexpr int FRAMES = S / HOP;    // 2048
constexpr int TROWS  = FRAMES + 1; // 2049
constexpr int S4     = S / 4;      // 131072 float4 per batch row

__global__ __launch_bounds__(256)
void glottal_flow_kernel(const float* __restrict__ wp,
                         const float* __restrict__ tables,
                         float* __restrict__ out)
{
    int i4 = blockIdx.x * 256 + threadIdx.x;   // global float4 index
    int b  = i4 >> 17;                         // / S4 (131072)
    int s  = (i4 & (S4 - 1)) << 2;             // sample index within batch row
    int f  = s >> 8;                           // frame (HOP = 256)
    int t  = s & (HOP - 1);                    // position within frame

    float4 w = __ldcs(reinterpret_cast<const float4*>(wp) + i4);  // streaming

    const float* rowF = tables + (size_t)(b * TROWS + f) * L; // floor frame row
    const float* rowC = rowF + L;                              // ceil frame row

    float wk[4] = {w.x, w.y, w.z, w.w};
    float r[4];

#pragma unroll
    for (int k = 0; k < 4; ++k) {
        float idx_raw = wk[k] * (float)L;
        int   fi      = (int)idx_raw;              // trunc toward zero (data >= 0)
        fi            = max(0, min(fi, L - 1));    // clip like reference
        float p       = idx_raw - (float)fi;
        int   fj      = fi + 1;
        if (fj == L) fj = 0;                       // padded column L == column 0

        float loF = __ldg(rowF + fi);
        float hiF = __ldg(rowF + fj);
        float loC = __ldg(rowC + fi);
        float hiC = __ldg(rowC + fj);

        float vF = fmaf(p, hiF - loF, loF);        // phase lerp, floor frame
        float vC = fmaf(p, hiC - loC, loC);        // phase lerp, ceil frame
        float p2 = (float)(t + k) * (1.0f / (float)HOP);
        r[k] = fmaf(p2, vC - vF, vF);              // frame lerp
    }

    __stcs(reinterpret_cast<float4*>(out) + i4,    // streaming store
           make_float4(r[0], r[1], r[2], r[3]));
}

extern "C" void kernel_launch(void* const* d_in, const int* in_sizes, int n_in,
                              void* d_out, int out_size)
{
    const float* wp     = (const float*)d_in[0];
    const float* tables = (const float*)d_in[1];
    float*       out    = (float*)d_out;

    constexpr int total4 = (B * S) / 4;            // 4,194,304 float4 work items
    glottal_flow_kernel<<<total4 / 256, 256>>>(wp, tables, out);
}